// round 2
// baseline (speedup 1.0000x reference)
#include <cuda_runtime.h>

// Problem dims
#define B_    8
#define N_    1024
#define R_    16384
#define DOBJ  32
#define DEFF  64
#define HID_  512
#define MROWS (B_ * R_)      // 131072
#define NROWS (B_ * N_)      // 8192

// ---------------- scratch (device globals; no allocations allowed) ----------
__device__ __align__(128) float g_node[MROWS * 64];    // node_obj [.,64]; later reused as edge [.,64]
__device__ __align__(128) float g_bufA[MROWS * HID_];  // h1; later h3 [.,64] at front
__device__ __align__(128) float g_bufB[MROWS * HID_];  // h2
__device__ __align__(128) float g_agg [NROWS * DEFF];  // agg [8192,64]
__device__ __align__(128) float g_upd [NROWS * 96];    // update_node [8192,96]
__device__ __align__(128) float g_hobj[NROWS * HID_];  // object hidden [8192,512]

// ---------------- gather: node_obj[b,r,col_off+d] = sum_n obj[b,n,d]*Rmat[n,r]
// block: 64 r-values, all 8 batches, all 32 d. 256 threads: d = tid&31, ry = tid>>5.
__global__ __launch_bounds__(256) void gather_kernel(
    const float* __restrict__ obj,   // [8,1024,32]
    const float* __restrict__ Rmat,  // [1024,16384]
    float* __restrict__ out,         // [8,16384,64]
    int col_off)
{
    const int NC = 16;
    __shared__ float obj_sh[NC][8][32];  // [n][b][d]
    __shared__ float R_sh[NC][64];       // [n][r]
    const int rtile = blockIdx.x * 64;
    const int tid = threadIdx.x;
    const int d = tid & 31, ry = tid >> 5;

    float acc[8][8];
    #pragma unroll
    for (int b = 0; b < 8; b++)
        #pragma unroll
        for (int j = 0; j < 8; j++) acc[b][j] = 0.f;

    for (int n0 = 0; n0 < N_; n0 += NC) {
        // load obj chunk: NC*8*32 = 4096 floats
        #pragma unroll
        for (int i = tid * 4; i < NC * 8 * 32; i += 256 * 4) {
            int n = i >> 8; int b = (i >> 5) & 7; int dd = i & 31;
            float4 v = *(const float4*)&obj[((size_t)b * N_ + n0 + n) * 32 + dd];
            *(float4*)&obj_sh[n][b][dd] = v;
        }
        // load R chunk: NC*64 = 1024 floats
        {
            int i = tid * 4;
            int n = i >> 6; int rr = i & 63;
            float4 v = *(const float4*)&Rmat[(size_t)(n0 + n) * R_ + rtile + rr];
            *(float4*)&R_sh[n][rr] = v;
        }
        __syncthreads();
        #pragma unroll
        for (int n = 0; n < NC; n++) {
            float rv[8], ov[8];
            #pragma unroll
            for (int j = 0; j < 8; j++) rv[j] = R_sh[n][ry + 8 * j];
            #pragma unroll
            for (int b = 0; b < 8; b++) ov[b] = obj_sh[n][b][d];
            #pragma unroll
            for (int b = 0; b < 8; b++)
                #pragma unroll
                for (int j = 0; j < 8; j++) acc[b][j] += ov[b] * rv[j];
        }
        __syncthreads();
    }
    #pragma unroll
    for (int b = 0; b < 8; b++)
        #pragma unroll
        for (int j = 0; j < 8; j++) {
            int r = rtile + ry + 8 * j;
            out[((size_t)b * R_ + r) * 64 + col_off + d] = acc[b][j];
        }
}

// ---------------- generic tiled SGEMM: C = act(A[M,K] @ W[K,N] + bias) -------
template<int BM, int BN, int BK, int TM, int TN, bool RELU>
__global__ __launch_bounds__((BM/TM)*(BN/TN)) void gemm_kernel(
    const float* __restrict__ A, const float* __restrict__ W,
    const float* __restrict__ bias, float* __restrict__ C,
    int M, int K, int N)
{
    __shared__ float As[BK][BM];
    __shared__ float Ws[BK][BN];
    const int nthr = (BM / TM) * (BN / TN);
    const int tid = threadIdx.x;
    const int tn = tid % (BN / TN);
    const int tm = tid / (BN / TN);
    const int row0 = blockIdx.y * BM;
    const int col0 = blockIdx.x * BN;

    float acc[TM][TN];
    #pragma unroll
    for (int m = 0; m < TM; m++)
        #pragma unroll
        for (int n = 0; n < TN; n++) acc[m][n] = 0.f;

    for (int k0 = 0; k0 < K; k0 += BK) {
        #pragma unroll
        for (int i = tid * 4; i < BM * BK; i += nthr * 4) {
            int r = i / BK, c = i % BK;
            float4 v = *(const float4*)&A[(size_t)(row0 + r) * K + k0 + c];
            As[c + 0][r] = v.x; As[c + 1][r] = v.y;
            As[c + 2][r] = v.z; As[c + 3][r] = v.w;
        }
        #pragma unroll
        for (int i = tid * 4; i < BK * BN; i += nthr * 4) {
            int r = i / BN, c = i % BN;
            *(float4*)&Ws[r][c] = *(const float4*)&W[(size_t)(k0 + r) * N + col0 + c];
        }
        __syncthreads();
        #pragma unroll
        for (int k = 0; k < BK; k++) {
            float a[TM], b[TN];
            #pragma unroll
            for (int m = 0; m < TM; m++) a[m] = As[k][tm * TM + m];
            #pragma unroll
            for (int n = 0; n < TN; n++) b[n] = Ws[k][tn * TN + n];
            #pragma unroll
            for (int m = 0; m < TM; m++)
                #pragma unroll
                for (int n = 0; n < TN; n++) acc[m][n] += a[m] * b[n];
        }
        __syncthreads();
    }
    #pragma unroll
    for (int m = 0; m < TM; m++) {
        int row = row0 + tm * TM + m;
        #pragma unroll
        for (int n = 0; n < TN; n++) {
            int col = col0 + tn * TN + n;
            float v = acc[m][n] + bias[col];
            if (RELU) v = fmaxf(v, 0.f);
            C[(size_t)row * N + col] = v;
        }
    }
}

// ---------------- aggregate: agg[b,n,e] = sum_r Rr[n,r]*edge[b,r,e] (split-K atomic)
__global__ __launch_bounds__(256) void agg_kernel(
    const float* __restrict__ Rrm,   // [1024,16384]
    const float* __restrict__ edge,  // [8,16384,64]
    float* __restrict__ agg)         // [8,1024,64] (pre-zeroed)
{
    const int KSPLIT = 8, KC = R_ / KSPLIT;  // 2048
    __shared__ float As[16][64];  // [k][n]
    __shared__ float Bs[16][64];  // [k][e]
    const int tid = threadIdx.x;
    const int tn = tid % 16, tm = tid / 16;
    const int n0 = blockIdx.x * 64;
    const int b = blockIdx.y;
    const int kbase = blockIdx.z * KC;
    const float* E = edge + (size_t)b * R_ * 64;

    float acc[4][4];
    #pragma unroll
    for (int m = 0; m < 4; m++)
        #pragma unroll
        for (int n = 0; n < 4; n++) acc[m][n] = 0.f;

    for (int k0 = kbase; k0 < kbase + KC; k0 += 16) {
        {   // A: 64 rows x 16 k, transpose into As[k][n]
            int i = tid * 4;
            int r = i / 16, c = i % 16;
            float4 v = *(const float4*)&Rrm[(size_t)(n0 + r) * R_ + k0 + c];
            As[c + 0][r] = v.x; As[c + 1][r] = v.y;
            As[c + 2][r] = v.z; As[c + 3][r] = v.w;
        }
        {   // B: 16 k x 64 e
            int i = tid * 4;
            int r = i / 64, c = i % 64;
            *(float4*)&Bs[r][c] = *(const float4*)&E[(size_t)(k0 + r) * 64 + c];
        }
        __syncthreads();
        #pragma unroll
        for (int k = 0; k < 16; k++) {
            float a[4], bb[4];
            #pragma unroll
            for (int m = 0; m < 4; m++) a[m] = As[k][tm * 4 + m];
            #pragma unroll
            for (int n = 0; n < 4; n++) bb[n] = Bs[k][tn * 4 + n];
            #pragma unroll
            for (int m = 0; m < 4; m++)
                #pragma unroll
                for (int n = 0; n < 4; n++) acc[m][n] += a[m] * bb[n];
        }
        __syncthreads();
    }
    #pragma unroll
    for (int m = 0; m < 4; m++)
        #pragma unroll
        for (int n = 0; n < 4; n++)
            atomicAdd(&agg[((size_t)b * N_ + n0 + tm * 4 + m) * 64 + tn * 4 + n],
                      acc[m][n]);
}

__global__ void zero_kernel(float* p, int n) {
    int i = blockIdx.x * blockDim.x + threadIdx.x;
    if (i < n) p[i] = 0.f;
}

__global__ void concat_kernel(const float* __restrict__ obj,
                              const float* __restrict__ agg,
                              float* __restrict__ upd) {
    int i = blockIdx.x * blockDim.x + threadIdx.x;
    if (i < NROWS * 96) {
        int row = i / 96, j = i % 96;
        upd[i] = (j < 32) ? obj[(size_t)row * 32 + j]
                          : agg[(size_t)row * 64 + (j - 32)];
    }
}

// ---------------- launch ----------------------------------------------------
extern "C" void kernel_launch(void* const* d_in, const int* in_sizes, int n_in,
                              void* d_out, int out_size) {
    const float* obj = (const float*)d_in[0];
    const float* Rs  = (const float*)d_in[1];
    const float* Rrm = (const float*)d_in[2];
    const float* rw1 = (const float*)d_in[3];  const float* rb1 = (const float*)d_in[4];
    const float* rw2 = (const float*)d_in[5];  const float* rb2 = (const float*)d_in[6];
    const float* rw3 = (const float*)d_in[7];  const float* rb3 = (const float*)d_in[8];
    const float* rw4 = (const float*)d_in[9];  const float* rb4 = (const float*)d_in[10];
    const float* ow1 = (const float*)d_in[11]; const float* ob1 = (const float*)d_in[12];
    const float* ow2 = (const float*)d_in[13]; const float* ob2 = (const float*)d_in[14];
    float* out = (float*)d_out;

    float *node, *bufA, *bufB, *agg, *upd, *hobj;
    cudaGetSymbolAddress((void**)&node, g_node);
    cudaGetSymbolAddress((void**)&bufA, g_bufA);
    cudaGetSymbolAddress((void**)&bufB, g_bufB);
    cudaGetSymbolAddress((void**)&agg,  g_agg);
    cudaGetSymbolAddress((void**)&upd,  g_upd);
    cudaGetSymbolAddress((void**)&hobj, g_hobj);

    // 1. gather src (Rs -> cols 0..31) and dst (Rr -> cols 32..63)
    gather_kernel<<<R_ / 64, 256>>>(obj, Rs,  node, 0);
    gather_kernel<<<R_ / 64, 256>>>(obj, Rrm, node, 32);

    // 2. relational MLP
    gemm_kernel<128, 128, 8, 8, 8, true><<<dim3(HID_ / 128, MROWS / 128), 256>>>(
        node, rw1, rb1, bufA, MROWS, 64, HID_);
    gemm_kernel<128, 128, 8, 8, 8, true><<<dim3(HID_ / 128, MROWS / 128), 256>>>(
        bufA, rw2, rb2, bufB, MROWS, HID_, HID_);
    gemm_kernel<128, 64, 8, 8, 4, true><<<dim3(1, MROWS / 128), 256>>>(
        bufB, rw3, rb3, bufA, MROWS, HID_, 64);           // h3 -> front of bufA
    gemm_kernel<128, 64, 8, 8, 4, true><<<dim3(1, MROWS / 128), 256>>>(
        bufA, rw4, rb4, node, MROWS, 64, 64);             // edge -> node buffer

    // 3. aggregate
    zero_kernel<<<(NROWS * DEFF + 255) / 256, 256>>>(agg, NROWS * DEFF);
    agg_kernel<<<dim3(N_ / 64, B_, 8), 256>>>(Rrm, node, agg);

    // 4. object MLP
    concat_kernel<<<(NROWS * 96 + 255) / 256, 256>>>(obj, agg, upd);
    gemm_kernel<128, 128, 8, 8, 8, true><<<dim3(HID_ / 128, NROWS / 128), 256>>>(
        upd, ow1, ob1, hobj, NROWS, 96, HID_);
    gemm_kernel<128, 32, 8, 8, 2, false><<<dim3(1, NROWS / 128), 256>>>(
        hobj, ow2, ob2, out, NROWS, HID_, 32);
}

// round 6
// speedup vs baseline: 4.0593x; 4.0593x over previous
#include <cuda_runtime.h>
#include <cstdint>

// Problem dims
#define B_    8
#define N_    1024
#define R_    16384
#define DOBJ  32
#define DEFF  64
#define HID_  512
#define MROWS (B_ * R_)      // 131072
#define NROWS (B_ * N_)      // 8192

// ---------------- scratch (device globals; no allocations allowed) ----------
__device__ __align__(128) float g_node[MROWS * 64];    // node_obj; later edgeT [16384,512] (same size)
__device__ __align__(128) float g_bufA[MROWS * HID_];  // h1; later h3 [.,64] at front
__device__ __align__(128) float g_bufB[MROWS * HID_];  // h2
__device__ __align__(128) float g_agg [N_ * 512];      // agg2 [1024, 512]  (col = b*64+e)
__device__ __align__(128) float g_upd [NROWS * 96];    // update_node [8192,96]
__device__ __align__(128) float g_hobj[NROWS * HID_];  // object hidden [8192,512]
__device__ __align__(128) float g_objT[N_ * 256];      // objT [1024, 256]  (col = b*32+d)

// ---------------- helpers ----------------------------------------------------
__device__ __forceinline__ float f2tf(float x) {
    uint32_t u;
    asm("cvt.rna.tf32.f32 %0, %1;" : "=r"(u) : "f"(x));
    return __uint_as_float(u);
}

__device__ __forceinline__ void mma_tf32(float d[4], const uint32_t a[4], const uint32_t b[2]) {
    asm volatile(
        "mma.sync.aligned.m16n8k8.row.col.f32.tf32.tf32.f32 "
        "{%0,%1,%2,%3},{%4,%5,%6,%7},{%8,%9},{%0,%1,%2,%3};\n"
        : "+f"(d[0]), "+f"(d[1]), "+f"(d[2]), "+f"(d[3])
        : "r"(a[0]), "r"(a[1]), "r"(a[2]), "r"(a[3]), "r"(b[0]), "r"(b[1]));
}

// MODE: 0 = C[row*N+col]=bias+act  1 = gather-scatter to node  2 = edgeT store  3 = split-K atomic
template<int MODE, bool RELU>
__device__ __forceinline__ void store_one(float* __restrict__ C, const float* __restrict__ bias,
                                          int row, int col, int N, int off, float v) {
    if (MODE == 0) {
        v += bias[col]; if (RELU) v = fmaxf(v, 0.f);
        C[(size_t)row * N + col] = v;
    } else if (MODE == 1) {
        int b = col >> 5, d = col & 31;
        C[(((size_t)b << 14) + row) * 64 + off + d] = v;
    } else if (MODE == 2) {
        v += bias[col]; if (RELU) v = fmaxf(v, 0.f);
        int b = row >> 14, r = row & 16383;
        C[(size_t)r * 512 + (b << 6) + col] = v;
    } else {
        atomicAdd(&C[(size_t)row * N + col], v);
    }
}

// ---------------- tf32 tensor-core GEMM: C = act(A[M,K] @ W[K,N] + bias) -----
// ATRANS: A physically stored [K][M] with row stride lda (used for Rs^T / Rr^T gathers).
// blockIdx.z * klen gives the K-range start (split-K for MODE 3).
template<int BM, int BN, int MODE, bool RELU, bool ATRANS>
__global__ __launch_bounds__((BM/64)*(BN/32)*32) void mma_gemm(
    const float* __restrict__ A, const float* __restrict__ W,
    const float* __restrict__ bias, float* __restrict__ C,
    int K, int N, int lda, int klen, int off)
{
    constexpr int BK = 16;
    constexpr int NW_N = BN / 32;
    constexpr int THREADS = (BM/64) * (BN/32) * 32;
    __shared__ float As[BK][BM + 8];
    __shared__ float Ws[BK][BN + 8];

    const int tid = threadIdx.x, lane = tid & 31, wid = tid >> 5;
    const int wm = (wid / NW_N) * 64, wn = (wid % NW_N) * 32;
    const int row0 = blockIdx.y * BM, col0 = blockIdx.x * BN;
    const int kstart = blockIdx.z * klen;

    float acc[4][4][4];
    #pragma unroll
    for (int mi = 0; mi < 4; mi++)
        #pragma unroll
        for (int ni = 0; ni < 4; ni++)
            #pragma unroll
            for (int j = 0; j < 4; j++) acc[mi][ni][j] = 0.f;

    for (int kk = kstart; kk < kstart + klen; kk += BK) {
        if (!ATRANS) {
            #pragma unroll
            for (int i = tid * 4; i < BM * BK; i += THREADS * 4) {
                int r = i / BK, c = i % BK;
                float4 v = *(const float4*)&A[(size_t)(row0 + r) * lda + kk + c];
                As[c + 0][r] = f2tf(v.x); As[c + 1][r] = f2tf(v.y);
                As[c + 2][r] = f2tf(v.z); As[c + 3][r] = f2tf(v.w);
            }
        } else {
            #pragma unroll
            for (int i = tid * 4; i < BK * BM; i += THREADS * 4) {
                int k = i / BM, m = i % BM;
                float4 v = *(const float4*)&A[(size_t)(kk + k) * lda + row0 + m];
                As[k][m + 0] = f2tf(v.x); As[k][m + 1] = f2tf(v.y);
                As[k][m + 2] = f2tf(v.z); As[k][m + 3] = f2tf(v.w);
            }
        }
        #pragma unroll
        for (int i = tid * 4; i < BK * BN; i += THREADS * 4) {
            int k = i / BN, n = i % BN;
            float4 v = *(const float4*)&W[(size_t)(kk + k) * N + col0 + n];
            Ws[k][n + 0] = f2tf(v.x); Ws[k][n + 1] = f2tf(v.y);
            Ws[k][n + 2] = f2tf(v.z); Ws[k][n + 3] = f2tf(v.w);
        }
        __syncthreads();

        #pragma unroll
        for (int s = 0; s < 2; s++) {
            const int k = s * 8;
            uint32_t a[4][4], b[4][2];
            const int lc = lane & 3, lg = lane >> 2;
            #pragma unroll
            for (int mi = 0; mi < 4; mi++) {
                int mb = wm + mi * 16 + lg;
                a[mi][0] = __float_as_uint(As[k + lc][mb]);
                a[mi][1] = __float_as_uint(As[k + lc][mb + 8]);
                a[mi][2] = __float_as_uint(As[k + lc + 4][mb]);
                a[mi][3] = __float_as_uint(As[k + lc + 4][mb + 8]);
            }
            #pragma unroll
            for (int ni = 0; ni < 4; ni++) {
                int nb = wn + ni * 8 + lg;
                b[ni][0] = __float_as_uint(Ws[k + lc][nb]);
                b[ni][1] = __float_as_uint(Ws[k + lc + 4][nb]);
            }
            #pragma unroll
            for (int mi = 0; mi < 4; mi++)
                #pragma unroll
                for (int ni = 0; ni < 4; ni++)
                    mma_tf32(acc[mi][ni], a[mi], b[ni]);
        }
        __syncthreads();
    }

    // epilogue
    const int lc = lane & 3, lg = lane >> 2;
    #pragma unroll
    for (int mi = 0; mi < 4; mi++) {
        int r0 = row0 + wm + mi * 16 + lg;
        #pragma unroll
        for (int ni = 0; ni < 4; ni++) {
            int c0 = col0 + wn + ni * 8 + lc * 2;
            store_one<MODE, RELU>(C, bias, r0,     c0,     N, off, acc[mi][ni][0]);
            store_one<MODE, RELU>(C, bias, r0,     c0 + 1, N, off, acc[mi][ni][1]);
            store_one<MODE, RELU>(C, bias, r0 + 8, c0,     N, off, acc[mi][ni][2]);
            store_one<MODE, RELU>(C, bias, r0 + 8, c0 + 1, N, off, acc[mi][ni][3]);
        }
    }
}

// ---------------- SIMT fp32 GEMM (kept for the tiny final layer) -------------
template<int BM, int BN, int BK, int TM, int TN, bool RELU>
__global__ __launch_bounds__((BM/TM)*(BN/TN)) void gemm_kernel(
    const float* __restrict__ A, const float* __restrict__ W,
    const float* __restrict__ bias, float* __restrict__ C,
    int M, int K, int N)
{
    __shared__ float As[BK][BM];
    __shared__ float Ws[BK][BN];
    const int nthr = (BM / TM) * (BN / TN);
    const int tid = threadIdx.x;
    const int tn = tid % (BN / TN);
    const int tm = tid / (BN / TN);
    const int row0 = blockIdx.y * BM;
    const int col0 = blockIdx.x * BN;

    float acc[TM][TN];
    #pragma unroll
    for (int m = 0; m < TM; m++)
        #pragma unroll
        for (int n = 0; n < TN; n++) acc[m][n] = 0.f;

    for (int k0 = 0; k0 < K; k0 += BK) {
        #pragma unroll
        for (int i = tid * 4; i < BM * BK; i += nthr * 4) {
            int r = i / BK, c = i % BK;
            float4 v = *(const float4*)&A[(size_t)(row0 + r) * K + k0 + c];
            As[c + 0][r] = v.x; As[c + 1][r] = v.y;
            As[c + 2][r] = v.z; As[c + 3][r] = v.w;
        }
        #pragma unroll
        for (int i = tid * 4; i < BK * BN; i += nthr * 4) {
            int r = i / BN, c = i % BN;
            *(float4*)&Ws[r][c] = *(const float4*)&W[(size_t)(k0 + r) * N + col0 + c];
        }
        __syncthreads();
        #pragma unroll
        for (int k = 0; k < BK; k++) {
            float a[TM], b[TN];
            #pragma unroll
            for (int m = 0; m < TM; m++) a[m] = As[k][tm * TM + m];
            #pragma unroll
            for (int n = 0; n < TN; n++) b[n] = Ws[k][tn * TN + n];
            #pragma unroll
            for (int m = 0; m < TM; m++)
                #pragma unroll
                for (int n = 0; n < TN; n++) acc[m][n] += a[m] * b[n];
        }
        __syncthreads();
    }
    #pragma unroll
    for (int m = 0; m < TM; m++) {
        int row = row0 + tm * TM + m;
        #pragma unroll
        for (int n = 0; n < TN; n++) {
            int col = col0 + tn * TN + n;
            float v = acc[m][n] + bias[col];
            if (RELU) v = fmaxf(v, 0.f);
            C[(size_t)row * N + col] = v;
        }
    }
}

// ---------------- small utility kernels --------------------------------------
__global__ void pack_objT_kernel(const float* __restrict__ obj, float* __restrict__ objT) {
    int i = blockIdx.x * blockDim.x + threadIdx.x;   // over 1024*256
    if (i < N_ * 256) {
        int n = i >> 8, c = i & 255;          // c = b*32+d
        int b = c >> 5, d = c & 31;
        objT[i] = obj[((size_t)b * N_ + n) * 32 + d];
    }
}

__global__ void zero_kernel(float* p, int n) {
    int i = blockIdx.x * blockDim.x + threadIdx.x;
    if (i < n) p[i] = 0.f;
}

__global__ void concat_kernel(const float* __restrict__ obj,
                              const float* __restrict__ agg2,   // [1024, 512], col=b*64+e
                              float* __restrict__ upd) {        // [8192, 96]
    int i = blockIdx.x * blockDim.x + threadIdx.x;
    if (i < NROWS * 96) {
        int row = i / 96, j = i % 96;
        int b = row >> 10, n = row & 1023;
        upd[i] = (j < 32) ? obj[(size_t)row * 32 + j]
                          : agg2[(size_t)n * 512 + (b << 6) + (j - 32)];
    }
}

// ---------------- launch ----------------------------------------------------
extern "C" void kernel_launch(void* const* d_in, const int* in_sizes, int n_in,
                              void* d_out, int out_size) {
    const float* obj = (const float*)d_in[0];
    const float* Rs  = (const float*)d_in[1];
    const float* Rrm = (const float*)d_in[2];
    const float* rw1 = (const float*)d_in[3];  const float* rb1 = (const float*)d_in[4];
    const float* rw2 = (const float*)d_in[5];  const float* rb2 = (const float*)d_in[6];
    const float* rw3 = (const float*)d_in[7];  const float* rb3 = (const float*)d_in[8];
    const float* rw4 = (const float*)d_in[9];  const float* rb4 = (const float*)d_in[10];
    const float* ow1 = (const float*)d_in[11]; const float* ob1 = (const float*)d_in[12];
    const float* ow2 = (const float*)d_in[13]; const float* ob2 = (const float*)d_in[14];
    float* out = (float*)d_out;

    float *node, *bufA, *bufB, *agg2, *upd, *hobj, *objT;
    cudaGetSymbolAddress((void**)&node, g_node);
    cudaGetSymbolAddress((void**)&bufA, g_bufA);
    cudaGetSymbolAddress((void**)&bufB, g_bufB);
    cudaGetSymbolAddress((void**)&agg2, g_agg);
    cudaGetSymbolAddress((void**)&upd,  g_upd);
    cudaGetSymbolAddress((void**)&hobj, g_hobj);
    cudaGetSymbolAddress((void**)&objT, g_objT);

    // 0. pack obj into [1024, 256] (col = b*32+d)
    pack_objT_kernel<<<(N_ * 256 + 255) / 256, 256>>>(obj, objT);

    // 1. gathers as GEMMs: C[r, b*32+d] = sum_n R[n,r] * objT[n, b*32+d]
    //    A = R^T (ATRANS, lda = R_), scatter epilogue into node[b,r,64]
    mma_gemm<128, 128, 1, false, true><<<dim3(2, R_ / 128), 256>>>(
        Rs,  objT, nullptr, node, N_, 256, R_, N_, 0);
    mma_gemm<128, 128, 1, false, true><<<dim3(2, R_ / 128), 256>>>(
        Rrm, objT, nullptr, node, N_, 256, R_, N_, 32);

    // 2. relational MLP (tf32 tensor cores)
    mma_gemm<128, 128, 0, true, false><<<dim3(HID_ / 128, MROWS / 128), 256>>>(
        node, rw1, rb1, bufA, 64, HID_, 64, 64, 0);
    mma_gemm<128, 128, 0, true, false><<<dim3(HID_ / 128, MROWS / 128), 256>>>(
        bufA, rw2, rb2, bufB, HID_, HID_, HID_, HID_, 0);
    mma_gemm<128, 64, 0, true, false><<<dim3(1, MROWS / 128), 128>>>(
        bufB, rw3, rb3, bufA, HID_, 64, HID_, HID_, 0);
    // layer4 writes transposed edge layout edgeT[r, b*64+e] into g_node (same size)
    mma_gemm<128, 64, 2, true, false><<<dim3(1, MROWS / 128), 128>>>(
        bufA, rw4, rb4, node, 64, 64, 64, 64, 0);

    // 3. aggregate: agg2[n, b*64+e] = sum_r Rr[n,r] * edgeT[r, b*64+e]  (split-K=8, atomic)
    zero_kernel<<<(N_ * 512 + 255) / 256, 256>>>(agg2, N_ * 512);
    mma_gemm<128, 128, 3, false, false><<<dim3(4, N_ / 128, 8), 256>>>(
        Rrm, node, nullptr, agg2, R_, 512, R_, R_ / 8, 0);

    // 4. object MLP
    concat_kernel<<<(NROWS * 96 + 255) / 256, 256>>>(obj, agg2, upd);
    mma_gemm<128, 128, 0, true, false><<<dim3(HID_ / 128, NROWS / 128), 256>>>(
        upd, ow1, ob1, hobj, 96, HID_, 96, 96, 0);
    // final tiny layer in exact fp32 SIMT (keeps output precision)
    gemm_kernel<128, 32, 8, 8, 2, false><<<dim3(1, NROWS / 128), 256>>>(
        hobj, ow2, ob2, out, NROWS, HID_, 32);
}